// round 2
// baseline (speedup 1.0000x reference)
#include <cuda_runtime.h>
#include <cstdint>

// Problem constants (from reference)
#define S_SCALE 64.0f
#define MARGIN  0.35f
#define BATCH   4096
#define NUM_CLASSES 50257

// Total elements = 4096 * 50257 = 205,852,672 ; divisible by 4 -> exact float4 tiling.
#define N_TOTAL (205852672)
#define N_VEC4  (N_TOTAL / 4)   // 51,463,168

// Kernel A: streaming scale, float4 vectorized.
__global__ void __launch_bounds__(256) cosface_scale_kernel(
    const float4* __restrict__ in, float4* __restrict__ out)
{
    unsigned int i = blockIdx.x * 256u + threadIdx.x;
    if (i < (unsigned int)N_VEC4) {
        float4 v = in[i];
        v.x *= S_SCALE;
        v.y *= S_SCALE;
        v.z *= S_SCALE;
        v.w *= S_SCALE;
        out[i] = v;
    }
}

// Kernel B: per-row fixup at (row, label). labels are int32 (JAX x64 disabled
// downcasts the reference's "int64" request). Bounds-guarded so a dtype
// surprise becomes a visible correctness error, never an illegal access.
__global__ void cosface_fixup_kernel(
    const float* __restrict__ logits,
    const int* __restrict__ labels,
    float* __restrict__ out)
{
    int row = blockIdx.x * blockDim.x + threadIdx.x;
    if (row < BATCH) {
        int lab = labels[row];
        if (lab >= 0 && lab < NUM_CLASSES) {
            size_t idx = (size_t)row * NUM_CLASSES + (size_t)lab;
            out[idx] = (logits[idx] - MARGIN) * S_SCALE;
        }
    }
}

extern "C" void kernel_launch(void* const* d_in, const int* in_sizes, int n_in,
                              void* d_out, int out_size)
{
    const float* logits = (const float*)d_in[0];
    const int*   labels = (const int*)d_in[1];
    float*       out    = (float*)d_out;

    (void)in_sizes; (void)n_in; (void)out_size;

    // Streaming scale: 51,463,168 float4 elems / 256 threads = 201,028 blocks exactly.
    dim3 grid((N_VEC4 + 255) / 256);
    cosface_scale_kernel<<<grid, 256>>>((const float4*)logits, (float4*)out);

    // Fixup the margin at (row, label).
    cosface_fixup_kernel<<<(BATCH + 255) / 256, 256>>>(logits, labels, out);
}